// round 5
// baseline (speedup 1.0000x reference)
#include <cuda_runtime.h>
#include <cuda_bf16.h>
#include <cstdint>
#include <cstddef>

#define N 4096
#define D 128
#define CHUNKS 6
#define JT 64
#define NT (N / JT)           // 64 j-tiles total
#define PITCH 272             // bytes per padded smem row (136 bf16)
#define TILE_BYTES (64 * PITCH)
#define PCOLS 264             // padded column count for prefix arrays (258 used)

// ---------------- device scratch ----------------
__device__ __nv_bfloat16 g_u_hi[N * D], g_u_lo[N * D];
__device__ __nv_bfloat16 g_p_hi[N * D], g_p_lo[N * D];
__device__ float g_uf[N * D];
__device__ float g_pf[N * D];
__device__ float g_partA[(size_t)CHUNKS * N * D];
__device__ float g_plsumA[CHUNKS * N];
__device__ float g_dis[N], g_hs[N], g_hd[N];
// attention (sorted-prefix) scratch
__device__ float g_hd_sorted[N];
__device__ int   g_perm[N];
__device__ float g_e1[N], g_e02[N];
__device__ float g_bsum[32 * PCOLS];
__device__ float g_bpref[33 * PCOLS];          // [32] row = totals
__device__ float g_P[(size_t)(N + 1) * PCOLS]; // exclusive prefix, row N = totals

// ---------------- helpers ----------------
__device__ __forceinline__ uint32_t pack2(float lo, float hi) {
    uint32_t d;
    asm("cvt.rn.bf16x2.f32 %0, %1, %2;" : "=r"(d) : "f"(hi), "f"(lo));
    return d;
}
__device__ __forceinline__ void mma_bf16(float* c, const uint32_t* a, uint32_t b0, uint32_t b1) {
    asm volatile(
        "mma.sync.aligned.m16n8k16.row.col.f32.bf16.bf16.f32 "
        "{%0,%1,%2,%3},{%4,%5,%6,%7},{%8,%9},{%0,%1,%2,%3};"
        : "+f"(c[0]), "+f"(c[1]), "+f"(c[2]), "+f"(c[3])
        : "r"(a[0]), "r"(a[1]), "r"(a[2]), "r"(a[3]), "r"(b0), "r"(b1));
}
#define LDSM4(r, addr)                                                              \
    asm volatile("ldmatrix.sync.aligned.m8n8.x4.shared.b16 {%0,%1,%2,%3},[%4];"     \
                 : "=r"((r)[0]), "=r"((r)[1]), "=r"((r)[2]), "=r"((r)[3]) : "r"(addr))
#define LDSM4T(r, addr)                                                                  \
    asm volatile("ldmatrix.sync.aligned.m8n8.x4.trans.shared.b16 {%0,%1,%2,%3},[%4];"    \
                 : "=r"((r)[0]), "=r"((r)[1]), "=r"((r)[2]), "=r"((r)[3]) : "r"(addr))

// ---------------- adj row sums -> d^{-1/2} ----------------
__global__ void rowsum_kernel(const float4* __restrict__ adj4) {
    const int i = blockIdx.x;
    float s = 0.f;
    for (int j = threadIdx.x; j < N / 4; j += 256) {
        float4 a = adj4[(size_t)i * (N / 4) + j];
        s += a.x + a.y + a.z + a.w;
    }
    __shared__ float red[256];
    red[threadIdx.x] = s;
    __syncthreads();
    #pragma unroll
    for (int off = 128; off > 0; off >>= 1) {
        if (threadIdx.x < off) red[threadIdx.x] += red[threadIdx.x + off];
        __syncthreads();
    }
    if (threadIdx.x == 0) g_dis[i] = rsqrtf(red[0] + 1e-8f);
}

// ---------------- u_hat = h @ W (fp32 + split bf16) ----------------
__global__ void uhat_kernel(const float* __restrict__ h, const float* __restrict__ W) {
    __shared__ float hrow[4][128];
    const int t = threadIdx.x;
    const int i0 = blockIdx.x * 4;
    #pragma unroll
    for (int r = 0; r < 4; r++) hrow[r][t] = h[(size_t)(i0 + r) * D + t];
    __syncthreads();
    float acc[4] = {0.f, 0.f, 0.f, 0.f};
    #pragma unroll 4
    for (int k = 0; k < 128; k++) {
        float wv = W[k * D + t];
        #pragma unroll
        for (int r = 0; r < 4; r++) acc[r] += hrow[r][k] * wv;
    }
    #pragma unroll
    for (int r = 0; r < 4; r++) {
        __nv_bfloat16 hi = __float2bfloat16_rn(acc[r]);
        float hf = __bfloat162float(hi);
        g_uf[(size_t)(i0 + r) * D + t]   = acc[r];
        g_u_hi[(size_t)(i0 + r) * D + t] = hi;
        g_u_lo[(size_t)(i0 + r) * D + t] = __float2bfloat16_rn(acc[r] - hf);
    }
}

// ---------------- hs = h@a_src, hd = h@a_dst ----------------
__global__ void hsd_kernel(const float4* __restrict__ h4, const float4* __restrict__ a4) {
    const int row  = blockIdx.x * 8 + (threadIdx.x >> 5);
    const int lane = threadIdx.x & 31;
    float4 hv = h4[(size_t)row * 32 + lane];
    float4 as = a4[lane];
    float4 ad = a4[32 + lane];
    float ps = hv.x * as.x + hv.y * as.y + hv.z * as.z + hv.w * as.w;
    float pd = hv.x * ad.x + hv.y * ad.y + hv.z * ad.z + hv.w * ad.w;
    #pragma unroll
    for (int o = 16; o > 0; o >>= 1) {
        ps += __shfl_xor_sync(0xffffffffu, ps, o);
        pd += __shfl_xor_sync(0xffffffffu, pd, o);
    }
    if (lane == 0) { g_hs[row] = ps; g_hd[row] = pd; }
}

// ---------------- bitonic sort of hd (ascending), + exp tables ----------------
__global__ void sort_kernel() {
    __shared__ float skey[N];
    __shared__ int   sidx[N];
    const int tid = threadIdx.x;
    for (int t = tid; t < N; t += 1024) { skey[t] = g_hd[t]; sidx[t] = t; }
    __syncthreads();
    for (int k = 2; k <= N; k <<= 1) {
        for (int j = k >> 1; j > 0; j >>= 1) {
            for (int t = tid; t < N; t += 1024) {
                int ixj = t ^ j;
                if (ixj > t) {
                    bool up = ((t & k) == 0);
                    float a = skey[t], b = skey[ixj];
                    if ((a > b) == up) {
                        skey[t] = b; skey[ixj] = a;
                        int tmp = sidx[t]; sidx[t] = sidx[ixj]; sidx[ixj] = tmp;
                    }
                }
            }
            __syncthreads();
        }
    }
    for (int t = tid; t < N; t += 1024) {
        float k = skey[t];
        g_hd_sorted[t] = k;
        g_perm[t] = sidx[t];
        g_e1[t]  = __expf(k);
        g_e02[t] = __expf(0.2f * k);
    }
}

// ---------------- 2-level Kahan prefix sums over 258 "columns" ----------------
// column c<128: e1[r]*u[perm[r]][c]; 128<=c<256: e02[r]*u[perm[r]][c-128];
// c==256: e1[r]; c==257: e02[r]
__device__ __forceinline__ void kadd(float& s, float& comp, float x) {
    float y = x - comp;
    float t = s + y;
    comp = (t - s) - y;
    s = t;
}
__global__ void scan_p1_kernel() {
    __shared__ int   sp[128];
    __shared__ float se1[128], se02[128];
    const int b = blockIdx.x, c = threadIdx.x;
    for (int r = threadIdx.x; r < 128; r += 288) {
        int rr = b * 128 + r;
        sp[r] = g_perm[rr]; se1[r] = g_e1[rr]; se02[r] = g_e02[rr];
    }
    __syncthreads();
    if (c < 258) {
        float s = 0.f, comp = 0.f;
        for (int r = 0; r < 128; r++) {
            float w = (c < 128 || c == 256) ? se1[r] : se02[r];
            float v = (c < 256) ? g_uf[(size_t)sp[r] * D + (c & 127)] : 1.f;
            kadd(s, comp, w * v);
        }
        g_bsum[b * PCOLS + c] = s;
    }
}
__global__ void scan_p2_kernel() {
    const int c = threadIdx.x;
    if (c >= 258) return;
    float run = 0.f, comp = 0.f;
    for (int b = 0; b < 32; b++) {
        float x = g_bsum[b * PCOLS + c];
        g_bpref[b * PCOLS + c] = run;
        kadd(run, comp, x);
    }
    g_bpref[32 * PCOLS + c] = run;                 // totals
    g_P[(size_t)N * PCOLS + c] = run;              // P[N] = totals
}
__global__ void scan_p3_kernel() {
    __shared__ int   sp[128];
    __shared__ float se1[128], se02[128];
    const int b = blockIdx.x, c = threadIdx.x;
    for (int r = threadIdx.x; r < 128; r += 288) {
        int rr = b * 128 + r;
        sp[r] = g_perm[rr]; se1[r] = g_e1[rr]; se02[r] = g_e02[rr];
    }
    __syncthreads();
    if (c < 258) {
        float s = g_bpref[b * PCOLS + c], comp = 0.f;
        for (int r = 0; r < 128; r++) {
            g_P[(size_t)(b * 128 + r) * PCOLS + c] = s;   // exclusive prefix
            float w = (c < 128 || c == 256) ? se1[r] : se02[r];
            float v = (c < 256) ? g_uf[(size_t)sp[r] * D + (c & 127)] : 1.f;
            kadd(s, comp, w * v);
        }
    }
}

// ---------------- tensor-core flash (routing scores only) ----------------
// score = dis_i*dis_j*adj[i,j] + (HAS_P ? p_i . u_j : 0)   -> g_partA / g_plsumA
template <bool HAS_P>
__global__ void __launch_bounds__(128, 3)
flash_mma(const float* __restrict__ adj) {
    extern __shared__ char sm[];
    __nv_bfloat16* u_hi_s = (__nv_bfloat16*)(sm);
    __nv_bfloat16* u_lo_s = (__nv_bfloat16*)(sm + TILE_BYTES);
    __nv_bfloat16* p_hi_s = (__nv_bfloat16*)(sm + 2 * TILE_BYTES);
    __nv_bfloat16* p_lo_s = (__nv_bfloat16*)(sm + 3 * TILE_BYTES);
    float* aux_s = (float*)(sm + (HAS_P ? 4 : 2) * TILE_BYTES);

    const int tid  = threadIdx.x;
    const int wid  = tid >> 5;
    const int lane = tid & 31;
    const int gid  = lane >> 2, tig = lane & 3;
    const int rb = blockIdx.x, chunk = blockIdx.y;
    const int r  = rb * 64 + wid * 16 + gid;
    const int r2 = r + 8;
    const int ts = (NT * chunk) / CHUNKS;
    const int te = (NT * (chunk + 1)) / CHUNKS;

    const uint32_t sm0 = (uint32_t)__cvta_generic_to_shared(sm);
    const uint32_t uhi_b = sm0, ulo_b = sm0 + TILE_BYTES;
    const uint32_t phi_b = sm0 + 2 * TILE_BYTES, plo_b = sm0 + 3 * TILE_BYTES;

    const int l7 = lane & 7;
    const int sA_off  = (((lane >> 3) & 1) * 8 + l7) * PITCH + ((lane >> 4) & 1) * 16;
    const int sBn_off = (((lane >> 4) & 1) * 8 + l7) * PITCH + ((lane >> 3) & 1) * 16;
    const int sBt_off = (((lane >> 3) & 1) * 8 + l7) * PITCH + ((lane >> 4) & 1) * 16;

    if (HAS_P) {
        for (int k = tid; k < 64 * 16; k += 128) {
            int row = k >> 4, c16 = k & 15;
            *(uint4*)((char*)p_hi_s + row * PITCH + c16 * 16) =
                *(const uint4*)(g_p_hi + (size_t)(rb * 64 + row) * D + c16 * 8);
            *(uint4*)((char*)p_lo_s + row * PITCH + c16 * 16) =
                *(const uint4*)(g_p_lo + (size_t)(rb * 64 + row) * D + c16 * 8);
        }
    }
    const float di_r = g_dis[r], di_r2 = g_dis[r2];

    float acc[16][4];
    #pragma unroll
    for (int i = 0; i < 16; i++)
        #pragma unroll
        for (int k = 0; k < 4; k++) acc[i][k] = 0.f;
    float lr = 0.f, lr2 = 0.f;

    #pragma unroll 1
    for (int t = ts; t < te; t++) {
        const int j0 = t * JT;
        __syncthreads();
        for (int k = tid; k < 64 * 16; k += 128) {
            int row = k >> 4, c16 = k & 15;
            *(uint4*)((char*)u_hi_s + row * PITCH + c16 * 16) =
                *(const uint4*)(g_u_hi + (size_t)(j0 + row) * D + c16 * 8);
            *(uint4*)((char*)u_lo_s + row * PITCH + c16 * 16) =
                *(const uint4*)(g_u_lo + (size_t)(j0 + row) * D + c16 * 8);
        }
        if (tid < 64) aux_s[tid] = g_dis[j0 + tid];
        __syncthreads();

        // ---- phase A: S = P . U^T (split bf16, 3 passes) ----
        float S[8][4];
        if (HAS_P) {
            #pragma unroll
            for (int i = 0; i < 8; i++)
                #pragma unroll
                for (int k = 0; k < 4; k++) S[i][k] = 0.f;
            #pragma unroll
            for (int kt = 0; kt < 8; kt++) {
                uint32_t ph[4], pl[4];
                LDSM4(ph, phi_b + wid * 16 * PITCH + 32 * kt + sA_off);
                LDSM4(pl, plo_b + wid * 16 * PITCH + 32 * kt + sA_off);
                #pragma unroll
                for (int jp = 0; jp < 4; jp++) {
                    uint32_t bh[4], bl[4];
                    uint32_t off = 16 * jp * PITCH + 32 * kt + sBn_off;
                    LDSM4(bh, uhi_b + off);
                    LDSM4(bl, ulo_b + off);
                    mma_bf16(S[2 * jp],     ph, bh[0], bh[1]);
                    mma_bf16(S[2 * jp + 1], ph, bh[2], bh[3]);
                    mma_bf16(S[2 * jp],     ph, bl[0], bl[1]);
                    mma_bf16(S[2 * jp + 1], ph, bl[2], bl[3]);
                    mma_bf16(S[2 * jp],     pl, bh[0], bh[1]);
                    mma_bf16(S[2 * jp + 1], pl, bh[2], bh[3]);
                }
            }
        }

        // ---- exp + repack into A-fragments (hi/lo) ----
        uint32_t ahi[4][4], alo[4][4];
        #pragma unroll
        for (int kp = 0; kp < 4; kp++) {
            #pragma unroll
            for (int half = 0; half < 2; half++) {
                const int jn = 2 * kp + half;
                const int c = 8 * jn + 2 * tig;
                float djc0 = aux_s[c], djc1 = aux_s[c + 1];
                float2 a_r  = __ldg((const float2*)(adj + (size_t)r  * N + j0 + c));
                float2 a_r2 = __ldg((const float2*)(adj + (size_t)r2 * N + j0 + c));
                float b00 = di_r  * djc0 * a_r.x,  b01 = di_r  * djc1 * a_r.y;
                float b10 = di_r2 * djc0 * a_r2.x, b11 = di_r2 * djc1 * a_r2.y;
                if (HAS_P) {
                    b00 += S[jn][0]; b01 += S[jn][1];
                    b10 += S[jn][2]; b11 += S[jn][3];
                }
                float e00 = __expf(b00), e01 = __expf(b01);
                float e10 = __expf(b10), e11 = __expf(b11);
                lr  += e00 + e01;
                lr2 += e10 + e11;
                uint32_t h0 = pack2(e00, e01);
                uint32_t h1 = pack2(e10, e11);
                float f00 = __uint_as_float(h0 << 16), f01 = __uint_as_float(h0 & 0xffff0000u);
                float f10 = __uint_as_float(h1 << 16), f11 = __uint_as_float(h1 & 0xffff0000u);
                ahi[kp][2 * half + 0] = h0;
                ahi[kp][2 * half + 1] = h1;
                alo[kp][2 * half + 0] = pack2(e00 - f00, e01 - f01);
                alo[kp][2 * half + 1] = pack2(e10 - f10, e11 - f11);
            }
        }

        // ---- phase B: ACC += PROB . U (split bf16, 3 passes) ----
        #pragma unroll
        for (int kp = 0; kp < 4; kp++) {
            #pragma unroll
            for (int dn2 = 0; dn2 < 8; dn2++) {
                uint32_t bh[4], bl[4];
                uint32_t off = 16 * kp * PITCH + 32 * dn2 + sBt_off;
                LDSM4T(bh, uhi_b + off);
                LDSM4T(bl, ulo_b + off);
                mma_bf16(acc[2 * dn2],     ahi[kp], bh[0], bh[1]);
                mma_bf16(acc[2 * dn2 + 1], ahi[kp], bh[2], bh[3]);
                mma_bf16(acc[2 * dn2],     ahi[kp], bl[0], bl[1]);
                mma_bf16(acc[2 * dn2 + 1], ahi[kp], bl[2], bl[3]);
                mma_bf16(acc[2 * dn2],     alo[kp], bh[0], bh[1]);
                mma_bf16(acc[2 * dn2 + 1], alo[kp], bh[2], bh[3]);
            }
        }
    }

    lr  += __shfl_xor_sync(0xffffffffu, lr, 1);
    lr  += __shfl_xor_sync(0xffffffffu, lr, 2);
    lr2 += __shfl_xor_sync(0xffffffffu, lr2, 1);
    lr2 += __shfl_xor_sync(0xffffffffu, lr2, 2);
    if (tig == 0) {
        g_plsumA[chunk * N + r]  = lr;
        g_plsumA[chunk * N + r2] = lr2;
    }
    #pragma unroll
    for (int dn = 0; dn < 16; dn++) {
        size_t o1 = ((size_t)chunk * N + r) * D + 8 * dn + 2 * tig;
        size_t o2 = ((size_t)chunk * N + r2) * D + 8 * dn + 2 * tig;
        *(float2*)(g_partA + o1) = make_float2(acc[dn][0], acc[dn][1]);
        *(float2*)(g_partA + o2) = make_float2(acc[dn][2], acc[dn][3]);
    }
}

// ---------------- reduce chunks, normalize, squash, update p ----------------
template <bool FIRST>
__global__ void reduce_squash_kernel() {
    const int row  = (blockIdx.x * 256 + threadIdx.x) >> 5;
    const int lane = threadIdx.x & 31;
    float4 s4 = make_float4(0.f, 0.f, 0.f, 0.f);
    float ls = 0.f;
    #pragma unroll
    for (int c = 0; c < CHUNKS; c++) {
        const float4 v = *(const float4*)(g_partA + ((size_t)c * N + row) * D + lane * 4);
        s4.x += v.x; s4.y += v.y; s4.z += v.z; s4.w += v.w;
        ls += g_plsumA[c * N + row];
    }
    float inv = 1.f / ls;
    s4.x *= inv; s4.y *= inv; s4.z *= inv; s4.w *= inv;
    float nn = s4.x * s4.x + s4.y * s4.y + s4.z * s4.z + s4.w * s4.w;
    #pragma unroll
    for (int o = 16; o > 0; o >>= 1) nn += __shfl_xor_sync(0xffffffffu, nn, o);
    float nrm = sqrtf(nn);
    float f = nrm / ((1.f + nrm) * (nrm + 1e-8f));
    float4 p;
    if (FIRST) {
        p = make_float4(f * s4.x, f * s4.y, f * s4.z, f * s4.w);
    } else {
        const float4 po = *(const float4*)(g_pf + (size_t)row * D + lane * 4);
        p = make_float4(po.x + f * s4.x, po.y + f * s4.y, po.z + f * s4.z, po.w + f * s4.w);
    }
    *(float4*)(g_pf + (size_t)row * D + lane * 4) = p;
    uint32_t h01 = pack2(p.x, p.y), h23 = pack2(p.z, p.w);
    *(uint32_t*)(g_p_hi + (size_t)row * D + lane * 4)     = h01;
    *(uint32_t*)(g_p_hi + (size_t)row * D + lane * 4 + 2) = h23;
    float fx = __uint_as_float(h01 << 16), fy = __uint_as_float(h01 & 0xffff0000u);
    float fz = __uint_as_float(h23 << 16), fw = __uint_as_float(h23 & 0xffff0000u);
    *(uint32_t*)(g_p_lo + (size_t)row * D + lane * 4)     = pack2(p.x - fx, p.y - fy);
    *(uint32_t*)(g_p_lo + (size_t)row * D + lane * 4 + 2) = pack2(p.z - fz, p.w - fw);
}

// ---------------- out = squash(0.6*s_route + 0.4*s_attn) ----------------
__global__ void final_kernel(float* __restrict__ out) {
    const int row  = (blockIdx.x * 256 + threadIdx.x) >> 5;
    const int lane = threadIdx.x & 31;
    // routing branch
    float4 sa = make_float4(0.f, 0.f, 0.f, 0.f);
    float la = 0.f;
    #pragma unroll
    for (int c = 0; c < CHUNKS; c++) {
        const float4 va = *(const float4*)(g_partA + ((size_t)c * N + row) * D + lane * 4);
        sa.x += va.x; sa.y += va.y; sa.z += va.z; sa.w += va.w;
        la += g_plsumA[c * N + row];
    }
    // attention branch:
    //   positive set (hs+hd >= 0): SUFFIX [lo, N) of hd-sorted order, weight e^{hs} e^{hd_j}
    //   negative set (hs+hd < 0):  PREFIX [0, lo),                    weight e^{0.2 hs} e^{0.2 hd_j}
    float hs = g_hs[row];
    float thr = -hs;
    int lo = 0, hi = N;
    while (lo < hi) {
        int m = (lo + hi) >> 1;
        if (g_hd_sorted[m] < thr) lo = m + 1; else hi = m;
    }
    const float* Pk = g_P + (size_t)lo * PCOLS;
    const float* Pt = g_P + (size_t)N * PCOLS;
    float e_hi = __expf(hs), e_lo = __expf(0.2f * hs);
    float4 p1  = *(const float4*)(Pk + lane * 4);
    float4 t1  = *(const float4*)(Pt + lane * 4);
    float4 p02 = *(const float4*)(Pk + 128 + lane * 4);
    float lattn = e_hi * (Pt[256] - Pk[256]) + e_lo * Pk[257];
    float4 num = make_float4(
        e_hi * (t1.x - p1.x) + e_lo * p02.x,
        e_hi * (t1.y - p1.y) + e_lo * p02.y,
        e_hi * (t1.z - p1.z) + e_lo * p02.z,
        e_hi * (t1.w - p1.w) + e_lo * p02.w);
    float ia = 0.6f / la, ib = 0.4f / lattn;
    float4 cm = make_float4(sa.x * ia + num.x * ib, sa.y * ia + num.y * ib,
                            sa.z * ia + num.z * ib, sa.w * ia + num.w * ib);
    float nn = cm.x * cm.x + cm.y * cm.y + cm.z * cm.z + cm.w * cm.w;
    #pragma unroll
    for (int o = 16; o > 0; o >>= 1) nn += __shfl_xor_sync(0xffffffffu, nn, o);
    float nrm = sqrtf(nn);
    float f = nrm / ((1.f + nrm) * (nrm + 1e-8f));
    *(float4*)(out + (size_t)row * D + lane * 4) =
        make_float4(cm.x * f, cm.y * f, cm.z * f, cm.w * f);
}

// ---------------- launch ----------------
extern "C" void kernel_launch(void* const* d_in, const int* in_sizes, int n_in,
                              void* d_out, int out_size) {
    (void)in_sizes; (void)n_in; (void)out_size;
    const float* h      = (const float*)d_in[0];
    const float* adj    = (const float*)d_in[1];
    const float* W      = (const float*)d_in[2];
    const float* attn_a = (const float*)d_in[3];
    float* out = (float*)d_out;

    static const size_t SMEM_NOP = 2 * TILE_BYTES + 256;
    static const size_t SMEM_P   = 4 * TILE_BYTES + 256;
    cudaFuncSetAttribute(flash_mma<true>,
                         cudaFuncAttributeMaxDynamicSharedMemorySize, (int)SMEM_P);

    rowsum_kernel<<<N, 256>>>((const float4*)adj);
    uhat_kernel<<<N / 4, 128>>>(h, W);
    hsd_kernel<<<N / 8, 256>>>((const float4*)h, (const float4*)attn_a);

    // attention branch precompute (sorted-prefix factorization)
    sort_kernel<<<1, 1024>>>();
    scan_p1_kernel<<<32, 288>>>();
    scan_p2_kernel<<<1, 288>>>();
    scan_p3_kernel<<<32, 288>>>();

    dim3 fg(N / 64, CHUNKS);
    flash_mma<false><<<fg, 128, SMEM_NOP>>>(adj);
    reduce_squash_kernel<true><<<N / 8, 256>>>();
    flash_mma<true><<<fg, 128, SMEM_P>>>(adj);
    reduce_squash_kernel<false><<<N / 8, 256>>>();
    flash_mma<true><<<fg, 128, SMEM_P>>>(adj);

    final_kernel<<<N / 8, 256>>>(out);
}

// round 6
// speedup vs baseline: 1.1190x; 1.1190x over previous
#include <cuda_runtime.h>
#include <cuda_bf16.h>
#include <cstdint>
#include <cstddef>

#define N 4096
#define D 128
#define CHUNKS 6
#define JT 64
#define NT (N / JT)           // 64 j-tiles total
#define PITCH 272             // bytes per padded smem row (136 bf16)
#define TILE_BYTES (64 * PITCH)
#define PCOLS 264             // padded column count for prefix arrays (258 used)

// ---------------- device scratch ----------------
__device__ __nv_bfloat16 g_u_hi[N * D], g_u_lo[N * D];
__device__ __nv_bfloat16 g_p_hi[N * D], g_p_lo[N * D];
__device__ float g_uf[N * D];
__device__ float g_pf[N * D];
__device__ float g_partA[(size_t)CHUNKS * N * D];
__device__ float g_plsumA[CHUNKS * N];
__device__ float g_dis[N], g_hs[N], g_hd[N];
// attention (sorted-prefix) scratch
__device__ float g_hd_sorted[N];
__device__ int   g_perm[N];
__device__ float g_e1[N], g_e02[N];
__device__ float g_bsum[32 * PCOLS];
__device__ float g_bpref[33 * PCOLS];          // [32] row = totals
__device__ float g_P[(size_t)(N + 1) * PCOLS]; // exclusive prefix, row N = totals

// ---------------- helpers ----------------
__device__ __forceinline__ uint32_t pack2(float lo, float hi) {
    uint32_t d;
    asm("cvt.rn.bf16x2.f32 %0, %1, %2;" : "=r"(d) : "f"(hi), "f"(lo));
    return d;
}
__device__ __forceinline__ void mma_bf16(float* c, const uint32_t* a, uint32_t b0, uint32_t b1) {
    asm volatile(
        "mma.sync.aligned.m16n8k16.row.col.f32.bf16.bf16.f32 "
        "{%0,%1,%2,%3},{%4,%5,%6,%7},{%8,%9},{%0,%1,%2,%3};"
        : "+f"(c[0]), "+f"(c[1]), "+f"(c[2]), "+f"(c[3])
        : "r"(a[0]), "r"(a[1]), "r"(a[2]), "r"(a[3]), "r"(b0), "r"(b1));
}
#define LDSM4(r, addr)                                                              \
    asm volatile("ldmatrix.sync.aligned.m8n8.x4.shared.b16 {%0,%1,%2,%3},[%4];"     \
                 : "=r"((r)[0]), "=r"((r)[1]), "=r"((r)[2]), "=r"((r)[3]) : "r"(addr))
#define LDSM4T(r, addr)                                                                  \
    asm volatile("ldmatrix.sync.aligned.m8n8.x4.trans.shared.b16 {%0,%1,%2,%3},[%4];"    \
                 : "=r"((r)[0]), "=r"((r)[1]), "=r"((r)[2]), "=r"((r)[3]) : "r"(addr))

// ---------------- adj row sums -> d^{-1/2} ----------------
__global__ void rowsum_kernel(const float4* __restrict__ adj4) {
    const int i = blockIdx.x;
    float s = 0.f;
    for (int j = threadIdx.x; j < N / 4; j += 256) {
        float4 a = adj4[(size_t)i * (N / 4) + j];
        s += a.x + a.y + a.z + a.w;
    }
    __shared__ float red[256];
    red[threadIdx.x] = s;
    __syncthreads();
    #pragma unroll
    for (int off = 128; off > 0; off >>= 1) {
        if (threadIdx.x < off) red[threadIdx.x] += red[threadIdx.x + off];
        __syncthreads();
    }
    if (threadIdx.x == 0) g_dis[i] = rsqrtf(red[0] + 1e-8f);
}

// ---------------- u_hat = h @ W (fp32 + split bf16) ----------------
__global__ void uhat_kernel(const float* __restrict__ h, const float* __restrict__ W) {
    __shared__ float hrow[4][128];
    const int t = threadIdx.x;
    const int i0 = blockIdx.x * 4;
    #pragma unroll
    for (int r = 0; r < 4; r++) hrow[r][t] = h[(size_t)(i0 + r) * D + t];
    __syncthreads();
    float acc[4] = {0.f, 0.f, 0.f, 0.f};
    #pragma unroll 4
    for (int k = 0; k < 128; k++) {
        float wv = W[k * D + t];
        #pragma unroll
        for (int r = 0; r < 4; r++) acc[r] += hrow[r][k] * wv;
    }
    #pragma unroll
    for (int r = 0; r < 4; r++) {
        __nv_bfloat16 hi = __float2bfloat16_rn(acc[r]);
        float hf = __bfloat162float(hi);
        g_uf[(size_t)(i0 + r) * D + t]   = acc[r];
        g_u_hi[(size_t)(i0 + r) * D + t] = hi;
        g_u_lo[(size_t)(i0 + r) * D + t] = __float2bfloat16_rn(acc[r] - hf);
    }
}

// ---------------- hs = h@a_src, hd = h@a_dst ----------------
__global__ void hsd_kernel(const float4* __restrict__ h4, const float4* __restrict__ a4) {
    const int row  = blockIdx.x * 8 + (threadIdx.x >> 5);
    const int lane = threadIdx.x & 31;
    float4 hv = h4[(size_t)row * 32 + lane];
    float4 as = a4[lane];
    float4 ad = a4[32 + lane];
    float ps = hv.x * as.x + hv.y * as.y + hv.z * as.z + hv.w * as.w;
    float pd = hv.x * ad.x + hv.y * ad.y + hv.z * ad.z + hv.w * ad.w;
    #pragma unroll
    for (int o = 16; o > 0; o >>= 1) {
        ps += __shfl_xor_sync(0xffffffffu, ps, o);
        pd += __shfl_xor_sync(0xffffffffu, pd, o);
    }
    if (lane == 0) { g_hs[row] = ps; g_hd[row] = pd; }
}

// ---------------- parallel counting-rank "sort" of hd (ascending) ----------------
// warp per element: rank(j) = #{k: hd_k < hd_j  ||  (hd_k == hd_j && k < j)}
// then scatter key/perm/exp tables to sorted position. Full-chip, ~4us.
__global__ void rank_kernel() {
    __shared__ float keys[N];
    const int tid = threadIdx.x;
    for (int t = tid; t < N; t += 256) keys[t] = g_hd[t];
    __syncthreads();
    const int wid = tid >> 5, lane = tid & 31;
    const int j = blockIdx.x * 8 + wid;
    const float my = keys[j];
    int rank = 0;
    #pragma unroll 4
    for (int k = lane; k < N; k += 32) {
        float v = keys[k];
        rank += (v < my || (v == my && k < j)) ? 1 : 0;
    }
    #pragma unroll
    for (int o = 16; o > 0; o >>= 1) rank += __shfl_xor_sync(0xffffffffu, rank, o);
    if (lane == 0) {
        g_hd_sorted[rank] = my;
        g_perm[rank] = j;
        g_e1[rank]  = __expf(my);
        g_e02[rank] = __expf(0.2f * my);
    }
}

// ---------------- 2-level Kahan prefix sums over 258 "columns" ----------------
// column c<128: e1[r]*u[perm[r]][c]; 128<=c<256: e02[r]*u[perm[r]][c-128];
// c==256: e1[r]; c==257: e02[r]
__device__ __forceinline__ void kadd(float& s, float& comp, float x) {
    float y = x - comp;
    float t = s + y;
    comp = (t - s) - y;
    s = t;
}
__global__ void scan_p1_kernel() {
    __shared__ int   sp[128];
    __shared__ float se1[128], se02[128];
    const int b = blockIdx.x, c = threadIdx.x;
    for (int r = threadIdx.x; r < 128; r += 288) {
        int rr = b * 128 + r;
        sp[r] = g_perm[rr]; se1[r] = g_e1[rr]; se02[r] = g_e02[rr];
    }
    __syncthreads();
    if (c < 258) {
        float s = 0.f, comp = 0.f;
        for (int r = 0; r < 128; r++) {
            float w = (c < 128 || c == 256) ? se1[r] : se02[r];
            float v = (c < 256) ? g_uf[(size_t)sp[r] * D + (c & 127)] : 1.f;
            kadd(s, comp, w * v);
        }
        g_bsum[b * PCOLS + c] = s;
    }
}
__global__ void scan_p2_kernel() {
    const int c = threadIdx.x;
    if (c >= 258) return;
    float run = 0.f, comp = 0.f;
    for (int b = 0; b < 32; b++) {
        float x = g_bsum[b * PCOLS + c];
        g_bpref[b * PCOLS + c] = run;
        kadd(run, comp, x);
    }
    g_bpref[32 * PCOLS + c] = run;                 // totals
    g_P[(size_t)N * PCOLS + c] = run;              // P[N] = totals
}
__global__ void scan_p3_kernel() {
    __shared__ int   sp[128];
    __shared__ float se1[128], se02[128];
    const int b = blockIdx.x, c = threadIdx.x;
    for (int r = threadIdx.x; r < 128; r += 288) {
        int rr = b * 128 + r;
        sp[r] = g_perm[rr]; se1[r] = g_e1[rr]; se02[r] = g_e02[rr];
    }
    __syncthreads();
    if (c < 258) {
        float s = g_bpref[b * PCOLS + c], comp = 0.f;
        for (int r = 0; r < 128; r++) {
            g_P[(size_t)(b * 128 + r) * PCOLS + c] = s;   // exclusive prefix
            float w = (c < 128 || c == 256) ? se1[r] : se02[r];
            float v = (c < 256) ? g_uf[(size_t)sp[r] * D + (c & 127)] : 1.f;
            kadd(s, comp, w * v);
        }
    }
}

// ---------------- tensor-core flash (routing scores only) ----------------
// score = dis_i*dis_j*adj[i,j] + (HAS_P ? p_i . u_j : 0)   -> g_partA / g_plsumA
template <bool HAS_P>
__global__ void __launch_bounds__(128, 3)
flash_mma(const float* __restrict__ adj) {
    extern __shared__ char sm[];
    __nv_bfloat16* u_hi_s = (__nv_bfloat16*)(sm);
    __nv_bfloat16* u_lo_s = (__nv_bfloat16*)(sm + TILE_BYTES);
    __nv_bfloat16* p_hi_s = (__nv_bfloat16*)(sm + 2 * TILE_BYTES);
    __nv_bfloat16* p_lo_s = (__nv_bfloat16*)(sm + 3 * TILE_BYTES);
    float* aux_s = (float*)(sm + (HAS_P ? 4 : 2) * TILE_BYTES);

    const int tid  = threadIdx.x;
    const int wid  = tid >> 5;
    const int lane = tid & 31;
    const int gid  = lane >> 2, tig = lane & 3;
    const int rb = blockIdx.x, chunk = blockIdx.y;
    const int r  = rb * 64 + wid * 16 + gid;
    const int r2 = r + 8;
    const int ts = (NT * chunk) / CHUNKS;
    const int te = (NT * (chunk + 1)) / CHUNKS;

    const uint32_t sm0 = (uint32_t)__cvta_generic_to_shared(sm);
    const uint32_t uhi_b = sm0, ulo_b = sm0 + TILE_BYTES;
    const uint32_t phi_b = sm0 + 2 * TILE_BYTES, plo_b = sm0 + 3 * TILE_BYTES;

    const int l7 = lane & 7;
    const int sA_off  = (((lane >> 3) & 1) * 8 + l7) * PITCH + ((lane >> 4) & 1) * 16;
    const int sBn_off = (((lane >> 4) & 1) * 8 + l7) * PITCH + ((lane >> 3) & 1) * 16;
    const int sBt_off = (((lane >> 3) & 1) * 8 + l7) * PITCH + ((lane >> 4) & 1) * 16;

    if (HAS_P) {
        for (int k = tid; k < 64 * 16; k += 128) {
            int row = k >> 4, c16 = k & 15;
            *(uint4*)((char*)p_hi_s + row * PITCH + c16 * 16) =
                *(const uint4*)(g_p_hi + (size_t)(rb * 64 + row) * D + c16 * 8);
            *(uint4*)((char*)p_lo_s + row * PITCH + c16 * 16) =
                *(const uint4*)(g_p_lo + (size_t)(rb * 64 + row) * D + c16 * 8);
        }
    }
    const float di_r = g_dis[r], di_r2 = g_dis[r2];

    float acc[16][4];
    #pragma unroll
    for (int i = 0; i < 16; i++)
        #pragma unroll
        for (int k = 0; k < 4; k++) acc[i][k] = 0.f;
    float lr = 0.f, lr2 = 0.f;

    #pragma unroll 1
    for (int t = ts; t < te; t++) {
        const int j0 = t * JT;
        __syncthreads();
        for (int k = tid; k < 64 * 16; k += 128) {
            int row = k >> 4, c16 = k & 15;
            *(uint4*)((char*)u_hi_s + row * PITCH + c16 * 16) =
                *(const uint4*)(g_u_hi + (size_t)(j0 + row) * D + c16 * 8);
            *(uint4*)((char*)u_lo_s + row * PITCH + c16 * 16) =
                *(const uint4*)(g_u_lo + (size_t)(j0 + row) * D + c16 * 8);
        }
        if (tid < 64) aux_s[tid] = g_dis[j0 + tid];
        __syncthreads();

        // ---- phase A: S = P . U^T (split bf16, 3 passes) ----
        float S[8][4];
        if (HAS_P) {
            #pragma unroll
            for (int i = 0; i < 8; i++)
                #pragma unroll
                for (int k = 0; k < 4; k++) S[i][k] = 0.f;
            #pragma unroll
            for (int kt = 0; kt < 8; kt++) {
                uint32_t ph[4], pl[4];
                LDSM4(ph, phi_b + wid * 16 * PITCH + 32 * kt + sA_off);
                LDSM4(pl, plo_b + wid * 16 * PITCH + 32 * kt + sA_off);
                #pragma unroll
                for (int jp = 0; jp < 4; jp++) {
                    uint32_t bh[4], bl[4];
                    uint32_t off = 16 * jp * PITCH + 32 * kt + sBn_off;
                    LDSM4(bh, uhi_b + off);
                    LDSM4(bl, ulo_b + off);
                    mma_bf16(S[2 * jp],     ph, bh[0], bh[1]);
                    mma_bf16(S[2 * jp + 1], ph, bh[2], bh[3]);
                    mma_bf16(S[2 * jp],     ph, bl[0], bl[1]);
                    mma_bf16(S[2 * jp + 1], ph, bl[2], bl[3]);
                    mma_bf16(S[2 * jp],     pl, bh[0], bh[1]);
                    mma_bf16(S[2 * jp + 1], pl, bh[2], bh[3]);
                }
            }
        }

        // ---- exp + repack into A-fragments (hi/lo) ----
        uint32_t ahi[4][4], alo[4][4];
        #pragma unroll
        for (int kp = 0; kp < 4; kp++) {
            #pragma unroll
            for (int half = 0; half < 2; half++) {
                const int jn = 2 * kp + half;
                const int c = 8 * jn + 2 * tig;
                float djc0 = aux_s[c], djc1 = aux_s[c + 1];
                float2 a_r  = __ldg((const float2*)(adj + (size_t)r  * N + j0 + c));
                float2 a_r2 = __ldg((const float2*)(adj + (size_t)r2 * N + j0 + c));
                float b00 = di_r  * djc0 * a_r.x,  b01 = di_r  * djc1 * a_r.y;
                float b10 = di_r2 * djc0 * a_r2.x, b11 = di_r2 * djc1 * a_r2.y;
                if (HAS_P) {
                    b00 += S[jn][0]; b01 += S[jn][1];
                    b10 += S[jn][2]; b11 += S[jn][3];
                }
                float e00 = __expf(b00), e01 = __expf(b01);
                float e10 = __expf(b10), e11 = __expf(b11);
                lr  += e00 + e01;
                lr2 += e10 + e11;
                uint32_t h0 = pack2(e00, e01);
                uint32_t h1 = pack2(e10, e11);
                float f00 = __uint_as_float(h0 << 16), f01 = __uint_as_float(h0 & 0xffff0000u);
                float f10 = __uint_as_float(h1 << 16), f11 = __uint_as_float(h1 & 0xffff0000u);
                ahi[kp][2 * half + 0] = h0;
                ahi[kp][2 * half + 1] = h1;
                alo[kp][2 * half + 0] = pack2(e00 - f00, e01 - f01);
                alo[kp][2 * half + 1] = pack2(e10 - f10, e11 - f11);
            }
        }

        // ---- phase B: ACC += PROB . U (split bf16, 3 passes) ----
        #pragma unroll
        for (int kp = 0; kp < 4; kp++) {
            #pragma unroll
            for (int dn2 = 0; dn2 < 8; dn2++) {
                uint32_t bh[4], bl[4];
                uint32_t off = 16 * kp * PITCH + 32 * dn2 + sBt_off;
                LDSM4T(bh, uhi_b + off);
                LDSM4T(bl, ulo_b + off);
                mma_bf16(acc[2 * dn2],     ahi[kp], bh[0], bh[1]);
                mma_bf16(acc[2 * dn2 + 1], ahi[kp], bh[2], bh[3]);
                mma_bf16(acc[2 * dn2],     ahi[kp], bl[0], bl[1]);
                mma_bf16(acc[2 * dn2 + 1], ahi[kp], bl[2], bl[3]);
                mma_bf16(acc[2 * dn2],     alo[kp], bh[0], bh[1]);
                mma_bf16(acc[2 * dn2 + 1], alo[kp], bh[2], bh[3]);
            }
        }
    }

    lr  += __shfl_xor_sync(0xffffffffu, lr, 1);
    lr  += __shfl_xor_sync(0xffffffffu, lr, 2);
    lr2 += __shfl_xor_sync(0xffffffffu, lr2, 1);
    lr2 += __shfl_xor_sync(0xffffffffu, lr2, 2);
    if (tig == 0) {
        g_plsumA[chunk * N + r]  = lr;
        g_plsumA[chunk * N + r2] = lr2;
    }
    #pragma unroll
    for (int dn = 0; dn < 16; dn++) {
        size_t o1 = ((size_t)chunk * N + r) * D + 8 * dn + 2 * tig;
        size_t o2 = ((size_t)chunk * N + r2) * D + 8 * dn + 2 * tig;
        *(float2*)(g_partA + o1) = make_float2(acc[dn][0], acc[dn][1]);
        *(float2*)(g_partA + o2) = make_float2(acc[dn][2], acc[dn][3]);
    }
}

// ---------------- reduce chunks, normalize, squash, update p ----------------
template <bool FIRST>
__global__ void reduce_squash_kernel() {
    const int row  = (blockIdx.x * 256 + threadIdx.x) >> 5;
    const int lane = threadIdx.x & 31;
    float4 s4 = make_float4(0.f, 0.f, 0.f, 0.f);
    float ls = 0.f;
    #pragma unroll
    for (int c = 0; c < CHUNKS; c++) {
        const float4 v = *(const float4*)(g_partA + ((size_t)c * N + row) * D + lane * 4);
        s4.x += v.x; s4.y += v.y; s4.z += v.z; s4.w += v.w;
        ls += g_plsumA[c * N + row];
    }
    float inv = 1.f / ls;
    s4.x *= inv; s4.y *= inv; s4.z *= inv; s4.w *= inv;
    float nn = s4.x * s4.x + s4.y * s4.y + s4.z * s4.z + s4.w * s4.w;
    #pragma unroll
    for (int o = 16; o > 0; o >>= 1) nn += __shfl_xor_sync(0xffffffffu, nn, o);
    float nrm = sqrtf(nn);
    float f = nrm / ((1.f + nrm) * (nrm + 1e-8f));
    float4 p;
    if (FIRST) {
        p = make_float4(f * s4.x, f * s4.y, f * s4.z, f * s4.w);
    } else {
        const float4 po = *(const float4*)(g_pf + (size_t)row * D + lane * 4);
        p = make_float4(po.x + f * s4.x, po.y + f * s4.y, po.z + f * s4.z, po.w + f * s4.w);
    }
    *(float4*)(g_pf + (size_t)row * D + lane * 4) = p;
    uint32_t h01 = pack2(p.x, p.y), h23 = pack2(p.z, p.w);
    *(uint32_t*)(g_p_hi + (size_t)row * D + lane * 4)     = h01;
    *(uint32_t*)(g_p_hi + (size_t)row * D + lane * 4 + 2) = h23;
    float fx = __uint_as_float(h01 << 16), fy = __uint_as_float(h01 & 0xffff0000u);
    float fz = __uint_as_float(h23 << 16), fw = __uint_as_float(h23 & 0xffff0000u);
    *(uint32_t*)(g_p_lo + (size_t)row * D + lane * 4)     = pack2(p.x - fx, p.y - fy);
    *(uint32_t*)(g_p_lo + (size_t)row * D + lane * 4 + 2) = pack2(p.z - fz, p.w - fw);
}

// ---------------- out = squash(0.6*s_route + 0.4*s_attn) ----------------
__global__ void final_kernel(float* __restrict__ out) {
    const int row  = (blockIdx.x * 256 + threadIdx.x) >> 5;
    const int lane = threadIdx.x & 31;
    // routing branch
    float4 sa = make_float4(0.f, 0.f, 0.f, 0.f);
    float la = 0.f;
    #pragma unroll
    for (int c = 0; c < CHUNKS; c++) {
        const float4 va = *(const float4*)(g_partA + ((size_t)c * N + row) * D + lane * 4);
        sa.x += va.x; sa.y += va.y; sa.z += va.z; sa.w += va.w;
        la += g_plsumA[c * N + row];
    }
    // attention branch:
    //   positive set (hs+hd >= 0): SUFFIX [lo, N) of hd-sorted order, weight e^{hs} e^{hd_j}
    //   negative set (hs+hd < 0):  PREFIX [0, lo),                    weight e^{0.2 hs} e^{0.2 hd_j}
    float hs = g_hs[row];
    float thr = -hs;
    int lo = 0, hi = N;
    while (lo < hi) {
        int m = (lo + hi) >> 1;
        if (g_hd_sorted[m] < thr) lo = m + 1; else hi = m;
    }
    const float* Pk = g_P + (size_t)lo * PCOLS;
    const float* Pt = g_P + (size_t)N * PCOLS;
    float e_hi = __expf(hs), e_lo = __expf(0.2f * hs);
    float4 p1  = *(const float4*)(Pk + lane * 4);
    float4 t1  = *(const float4*)(Pt + lane * 4);
    float4 p02 = *(const float4*)(Pk + 128 + lane * 4);
    float lattn = e_hi * (Pt[256] - Pk[256]) + e_lo * Pk[257];
    float4 num = make_float4(
        e_hi * (t1.x - p1.x) + e_lo * p02.x,
        e_hi * (t1.y - p1.y) + e_lo * p02.y,
        e_hi * (t1.z - p1.z) + e_lo * p02.z,
        e_hi * (t1.w - p1.w) + e_lo * p02.w);
    float ia = 0.6f / la, ib = 0.4f / lattn;
    float4 cm = make_float4(sa.x * ia + num.x * ib, sa.y * ia + num.y * ib,
                            sa.z * ia + num.z * ib, sa.w * ia + num.w * ib);
    float nn = cm.x * cm.x + cm.y * cm.y + cm.z * cm.z + cm.w * cm.w;
    #pragma unroll
    for (int o = 16; o > 0; o >>= 1) nn += __shfl_xor_sync(0xffffffffu, nn, o);
    float nrm = sqrtf(nn);
    float f = nrm / ((1.f + nrm) * (nrm + 1e-8f));
    *(float4*)(out + (size_t)row * D + lane * 4) =
        make_float4(cm.x * f, cm.y * f, cm.z * f, cm.w * f);
}

// ---------------- launch ----------------
extern "C" void kernel_launch(void* const* d_in, const int* in_sizes, int n_in,
                              void* d_out, int out_size) {
    (void)in_sizes; (void)n_in; (void)out_size;
    const float* h      = (const float*)d_in[0];
    const float* adj    = (const float*)d_in[1];
    const float* W      = (const float*)d_in[2];
    const float* attn_a = (const float*)d_in[3];
    float* out = (float*)d_out;

    static const size_t SMEM_NOP = 2 * TILE_BYTES + 256;
    static const size_t SMEM_P   = 4 * TILE_BYTES + 256;
    cudaFuncSetAttribute(flash_mma<true>,
                         cudaFuncAttributeMaxDynamicSharedMemorySize, (int)SMEM_P);

    rowsum_kernel<<<N, 256>>>((const float4*)adj);
    uhat_kernel<<<N / 4, 128>>>(h, W);
    hsd_kernel<<<N / 8, 256>>>((const float4*)h, (const float4*)attn_a);

    // attention branch precompute (sorted-prefix factorization)
    rank_kernel<<<N / 8, 256>>>();
    scan_p1_kernel<<<32, 288>>>();
    scan_p2_kernel<<<1, 288>>>();
    scan_p3_kernel<<<32, 288>>>();

    dim3 fg(N / 64, CHUNKS);
    flash_mma<false><<<fg, 128, SMEM_NOP>>>(adj);
    reduce_squash_kernel<true><<<N / 8, 256>>>();
    flash_mma<true><<<fg, 128, SMEM_P>>>(adj);
    reduce_squash_kernel<false><<<N / 8, 256>>>();
    flash_mma<true><<<fg, 128, SMEM_P>>>(adj);

    final_kernel<<<N / 8, 256>>>(out);
}

// round 7
// speedup vs baseline: 1.2927x; 1.1552x over previous
#include <cuda_runtime.h>
#include <cuda_bf16.h>
#include <cstdint>
#include <cstddef>

#define N 4096
#define D 128
#define CHUNKS 6
#define JT 64
#define NT (N / JT)           // 64 j-tiles total
#define PITCH 272             // bytes per padded smem row (136 bf16)
#define TILE_BYTES (64 * PITCH)
#define PCOLS 264             // padded column count for prefix arrays (258 used)

// ---------------- device scratch ----------------
__device__ __nv_bfloat16 g_u_hi[N * D], g_u_lo[N * D];
__device__ __nv_bfloat16 g_p_hi[N * D];
__device__ float g_uf[N * D];
__device__ float g_pf[N * D];
__device__ float g_partA[(size_t)CHUNKS * N * D];
__device__ float g_plsumA[CHUNKS * N];
__device__ float g_dis[N], g_hs[N], g_hd[N];
// attention (sorted-prefix) scratch
__device__ float g_hd_sorted[N];
__device__ int   g_perm[N];
__device__ float g_e1[N], g_e02[N];
__device__ float g_bsum[32 * PCOLS];
__device__ float g_bpref[33 * PCOLS];          // [32] row = totals
__device__ float g_P[(size_t)(N + 1) * PCOLS]; // exclusive prefix, row N = totals

// ---------------- helpers ----------------
__device__ __forceinline__ uint32_t pack2(float lo, float hi) {
    uint32_t d;
    asm("cvt.rn.bf16x2.f32 %0, %1, %2;" : "=r"(d) : "f"(hi), "f"(lo));
    return d;
}
__device__ __forceinline__ void mma_bf16(float* c, const uint32_t* a, uint32_t b0, uint32_t b1) {
    asm volatile(
        "mma.sync.aligned.m16n8k16.row.col.f32.bf16.bf16.f32 "
        "{%0,%1,%2,%3},{%4,%5,%6,%7},{%8,%9},{%0,%1,%2,%3};"
        : "+f"(c[0]), "+f"(c[1]), "+f"(c[2]), "+f"(c[3])
        : "r"(a[0]), "r"(a[1]), "r"(a[2]), "r"(a[3]), "r"(b0), "r"(b1));
}
#define LDSM4(r, addr)                                                              \
    asm volatile("ldmatrix.sync.aligned.m8n8.x4.shared.b16 {%0,%1,%2,%3},[%4];"     \
                 : "=r"((r)[0]), "=r"((r)[1]), "=r"((r)[2]), "=r"((r)[3]) : "r"(addr))
#define LDSM4T(r, addr)                                                                  \
    asm volatile("ldmatrix.sync.aligned.m8n8.x4.trans.shared.b16 {%0,%1,%2,%3},[%4];"    \
                 : "=r"((r)[0]), "=r"((r)[1]), "=r"((r)[2]), "=r"((r)[3]) : "r"(addr))

// ---------------- adj row sums -> d^{-1/2} ----------------
__global__ void rowsum_kernel(const float4* __restrict__ adj4) {
    const int i = blockIdx.x;
    float s = 0.f;
    for (int j = threadIdx.x; j < N / 4; j += 256) {
        float4 a = adj4[(size_t)i * (N / 4) + j];
        s += a.x + a.y + a.z + a.w;
    }
    __shared__ float red[256];
    red[threadIdx.x] = s;
    __syncthreads();
    #pragma unroll
    for (int off = 128; off > 0; off >>= 1) {
        if (threadIdx.x < off) red[threadIdx.x] += red[threadIdx.x + off];
        __syncthreads();
    }
    if (threadIdx.x == 0) g_dis[i] = rsqrtf(red[0] + 1e-8f);
}

// ---------------- u_hat = h @ W (fp32 + split bf16) ----------------
__global__ void uhat_kernel(const float* __restrict__ h, const float* __restrict__ W) {
    __shared__ float hrow[4][128];
    const int t = threadIdx.x;
    const int i0 = blockIdx.x * 4;
    #pragma unroll
    for (int r = 0; r < 4; r++) hrow[r][t] = h[(size_t)(i0 + r) * D + t];
    __syncthreads();
    float acc[4] = {0.f, 0.f, 0.f, 0.f};
    #pragma unroll 4
    for (int k = 0; k < 128; k++) {
        float wv = W[k * D + t];
        #pragma unroll
        for (int r = 0; r < 4; r++) acc[r] += hrow[r][k] * wv;
    }
    #pragma unroll
    for (int r = 0; r < 4; r++) {
        __nv_bfloat16 hi = __float2bfloat16_rn(acc[r]);
        float hf = __bfloat162float(hi);
        g_uf[(size_t)(i0 + r) * D + t]   = acc[r];
        g_u_hi[(size_t)(i0 + r) * D + t] = hi;
        g_u_lo[(size_t)(i0 + r) * D + t] = __float2bfloat16_rn(acc[r] - hf);
    }
}

// ---------------- hs = h@a_src, hd = h@a_dst ----------------
__global__ void hsd_kernel(const float4* __restrict__ h4, const float4* __restrict__ a4) {
    const int row  = blockIdx.x * 8 + (threadIdx.x >> 5);
    const int lane = threadIdx.x & 31;
    float4 hv = h4[(size_t)row * 32 + lane];
    float4 as = a4[lane];
    float4 ad = a4[32 + lane];
    float ps = hv.x * as.x + hv.y * as.y + hv.z * as.z + hv.w * as.w;
    float pd = hv.x * ad.x + hv.y * ad.y + hv.z * ad.z + hv.w * ad.w;
    #pragma unroll
    for (int o = 16; o > 0; o >>= 1) {
        ps += __shfl_xor_sync(0xffffffffu, ps, o);
        pd += __shfl_xor_sync(0xffffffffu, pd, o);
    }
    if (lane == 0) { g_hs[row] = ps; g_hd[row] = pd; }
}

// ---------------- parallel counting-rank "sort" of hd (ascending) ----------------
// warp per element, float4-vectorized smem scan.
__global__ void rank_kernel() {
    __shared__ float4 keys4[N / 4];
    const int tid = threadIdx.x;
    float* keys = (float*)keys4;
    for (int t = tid; t < N; t += 256) keys[t] = g_hd[t];
    __syncthreads();
    const int wid = tid >> 5, lane = tid & 31;
    const int j = blockIdx.x * 8 + wid;
    const float my = keys[j];
    int rank = 0;
    #pragma unroll 4
    for (int k4 = lane; k4 < N / 4; k4 += 32) {
        float4 v = keys4[k4];
        int k = 4 * k4;
        rank += (v.x < my || (v.x == my && k     < j)) ? 1 : 0;
        rank += (v.y < my || (v.y == my && k + 1 < j)) ? 1 : 0;
        rank += (v.z < my || (v.z == my && k + 2 < j)) ? 1 : 0;
        rank += (v.w < my || (v.w == my && k + 3 < j)) ? 1 : 0;
    }
    #pragma unroll
    for (int o = 16; o > 0; o >>= 1) rank += __shfl_xor_sync(0xffffffffu, rank, o);
    if (lane == 0) {
        g_hd_sorted[rank] = my;
        g_perm[rank] = j;
        g_e1[rank]  = __expf(my);
        g_e02[rank] = __expf(0.2f * my);
    }
}

// ---------------- 2-level Kahan prefix sums over 258 "columns" ----------------
__device__ __forceinline__ void kadd(float& s, float& comp, float x) {
    float y = x - comp;
    float t = s + y;
    comp = (t - s) - y;
    s = t;
}
__global__ void scan_p1_kernel() {
    __shared__ int   sp[128];
    __shared__ float se1[128], se02[128];
    const int b = blockIdx.x, c = threadIdx.x;
    for (int r = threadIdx.x; r < 128; r += 288) {
        int rr = b * 128 + r;
        sp[r] = g_perm[rr]; se1[r] = g_e1[rr]; se02[r] = g_e02[rr];
    }
    __syncthreads();
    if (c < 258) {
        float s = 0.f, comp = 0.f;
        for (int r = 0; r < 128; r++) {
            float w = (c < 128 || c == 256) ? se1[r] : se02[r];
            float v = (c < 256) ? g_uf[(size_t)sp[r] * D + (c & 127)] : 1.f;
            kadd(s, comp, w * v);
        }
        g_bsum[b * PCOLS + c] = s;
    }
}
__global__ void scan_p2_kernel() {
    const int c = threadIdx.x;
    if (c >= 258) return;
    float run = 0.f, comp = 0.f;
    for (int b = 0; b < 32; b++) {
        float x = g_bsum[b * PCOLS + c];
        g_bpref[b * PCOLS + c] = run;
        kadd(run, comp, x);
    }
    g_bpref[32 * PCOLS + c] = run;                 // totals
    g_P[(size_t)N * PCOLS + c] = run;              // P[N] = totals
}
__global__ void scan_p3_kernel() {
    __shared__ int   sp[128];
    __shared__ float se1[128], se02[128];
    const int b = blockIdx.x, c = threadIdx.x;
    for (int r = threadIdx.x; r < 128; r += 288) {
        int rr = b * 128 + r;
        sp[r] = g_perm[rr]; se1[r] = g_e1[rr]; se02[r] = g_e02[rr];
    }
    __syncthreads();
    if (c < 258) {
        float s = g_bpref[b * PCOLS + c], comp = 0.f;
        for (int r = 0; r < 128; r++) {
            g_P[(size_t)(b * 128 + r) * PCOLS + c] = s;   // exclusive prefix
            float w = (c < 128 || c == 256) ? se1[r] : se02[r];
            float v = (c < 256) ? g_uf[(size_t)sp[r] * D + (c & 127)] : 1.f;
            kadd(s, comp, w * v);
        }
    }
}

// ---------------- tensor-core flash (routing scores only) ----------------
// score = dis_i*dis_j*adj[i,j] + (HAS_P ? p_i . u_j : 0)   -> g_partA / g_plsumA
// Precision scheme: U split hi/lo bf16 (2 passes), P and probs bf16-hi only.
template <bool HAS_P>
__global__ void __launch_bounds__(128, 3)
flash_mma(const float* __restrict__ adj) {
    extern __shared__ char sm[];
    __nv_bfloat16* u_hi_s = (__nv_bfloat16*)(sm);
    __nv_bfloat16* u_lo_s = (__nv_bfloat16*)(sm + TILE_BYTES);
    __nv_bfloat16* p_hi_s = (__nv_bfloat16*)(sm + 2 * TILE_BYTES);
    float* aux_s = (float*)(sm + (HAS_P ? 3 : 2) * TILE_BYTES);

    const int tid  = threadIdx.x;
    const int wid  = tid >> 5;
    const int lane = tid & 31;
    const int gid  = lane >> 2, tig = lane & 3;
    const int rb = blockIdx.x, chunk = blockIdx.y;
    const int r  = rb * 64 + wid * 16 + gid;
    const int r2 = r + 8;
    const int ts = (NT * chunk) / CHUNKS;
    const int te = (NT * (chunk + 1)) / CHUNKS;

    const uint32_t sm0 = (uint32_t)__cvta_generic_to_shared(sm);
    const uint32_t uhi_b = sm0, ulo_b = sm0 + TILE_BYTES;
    const uint32_t phi_b = sm0 + 2 * TILE_BYTES;

    const int l7 = lane & 7;
    const int sA_off  = (((lane >> 3) & 1) * 8 + l7) * PITCH + ((lane >> 4) & 1) * 16;
    const int sBn_off = (((lane >> 4) & 1) * 8 + l7) * PITCH + ((lane >> 3) & 1) * 16;
    const int sBt_off = (((lane >> 3) & 1) * 8 + l7) * PITCH + ((lane >> 4) & 1) * 16;

    if (HAS_P) {
        for (int k = tid; k < 64 * 16; k += 128) {
            int row = k >> 4, c16 = k & 15;
            *(uint4*)((char*)p_hi_s + row * PITCH + c16 * 16) =
                *(const uint4*)(g_p_hi + (size_t)(rb * 64 + row) * D + c16 * 8);
        }
    }
    const float di_r = g_dis[r], di_r2 = g_dis[r2];

    float acc[16][4];
    #pragma unroll
    for (int i = 0; i < 16; i++)
        #pragma unroll
        for (int k = 0; k < 4; k++) acc[i][k] = 0.f;
    float lr = 0.f, lr2 = 0.f;

    #pragma unroll 1
    for (int t = ts; t < te; t++) {
        const int j0 = t * JT;
        __syncthreads();
        for (int k = tid; k < 64 * 16; k += 128) {
            int row = k >> 4, c16 = k & 15;
            *(uint4*)((char*)u_hi_s + row * PITCH + c16 * 16) =
                *(const uint4*)(g_u_hi + (size_t)(j0 + row) * D + c16 * 8);
            *(uint4*)((char*)u_lo_s + row * PITCH + c16 * 16) =
                *(const uint4*)(g_u_lo + (size_t)(j0 + row) * D + c16 * 8);
        }
        if (tid < 64) aux_s[tid] = g_dis[j0 + tid];
        __syncthreads();

        // ---- phase A: S = P_hi . (U_hi + U_lo)^T ----
        float S[8][4];
        if (HAS_P) {
            #pragma unroll
            for (int i = 0; i < 8; i++)
                #pragma unroll
                for (int k = 0; k < 4; k++) S[i][k] = 0.f;
            #pragma unroll
            for (int kt = 0; kt < 8; kt++) {
                uint32_t ph[4];
                LDSM4(ph, phi_b + wid * 16 * PITCH + 32 * kt + sA_off);
                #pragma unroll
                for (int jp = 0; jp < 4; jp++) {
                    uint32_t bh[4], bl[4];
                    uint32_t off = 16 * jp * PITCH + 32 * kt + sBn_off;
                    LDSM4(bh, uhi_b + off);
                    LDSM4(bl, ulo_b + off);
                    mma_bf16(S[2 * jp],     ph, bh[0], bh[1]);
                    mma_bf16(S[2 * jp + 1], ph, bh[2], bh[3]);
                    mma_bf16(S[2 * jp],     ph, bl[0], bl[1]);
                    mma_bf16(S[2 * jp + 1], ph, bl[2], bl[3]);
                }
            }
        }

        // ---- exp + repack probs into bf16-hi A-fragments ----
        uint32_t ahi[4][4];
        #pragma unroll
        for (int kp = 0; kp < 4; kp++) {
            #pragma unroll
            for (int half = 0; half < 2; half++) {
                const int jn = 2 * kp + half;
                const int c = 8 * jn + 2 * tig;
                float djc0 = aux_s[c], djc1 = aux_s[c + 1];
                float2 a_r  = __ldg((const float2*)(adj + (size_t)r  * N + j0 + c));
                float2 a_r2 = __ldg((const float2*)(adj + (size_t)r2 * N + j0 + c));
                float b00 = di_r  * djc0 * a_r.x,  b01 = di_r  * djc1 * a_r.y;
                float b10 = di_r2 * djc0 * a_r2.x, b11 = di_r2 * djc1 * a_r2.y;
                if (HAS_P) {
                    b00 += S[jn][0]; b01 += S[jn][1];
                    b10 += S[jn][2]; b11 += S[jn][3];
                }
                float e00 = __expf(b00), e01 = __expf(b01);
                float e10 = __expf(b10), e11 = __expf(b11);
                lr  += e00 + e01;
                lr2 += e10 + e11;
                ahi[kp][2 * half + 0] = pack2(e00, e01);
                ahi[kp][2 * half + 1] = pack2(e10, e11);
            }
        }

        // ---- phase B: ACC += PROB_hi . (U_hi + U_lo) ----
        #pragma unroll
        for (int kp = 0; kp < 4; kp++) {
            #pragma unroll
            for (int dn2 = 0; dn2 < 8; dn2++) {
                uint32_t bh[4], bl[4];
                uint32_t off = 16 * kp * PITCH + 32 * dn2 + sBt_off;
                LDSM4T(bh, uhi_b + off);
                LDSM4T(bl, ulo_b + off);
                mma_bf16(acc[2 * dn2],     ahi[kp], bh[0], bh[1]);
                mma_bf16(acc[2 * dn2 + 1], ahi[kp], bh[2], bh[3]);
                mma_bf16(acc[2 * dn2],     ahi[kp], bl[0], bl[1]);
                mma_bf16(acc[2 * dn2 + 1], ahi[kp], bl[2], bl[3]);
            }
        }
    }

    lr  += __shfl_xor_sync(0xffffffffu, lr, 1);
    lr  += __shfl_xor_sync(0xffffffffu, lr, 2);
    lr2 += __shfl_xor_sync(0xffffffffu, lr2, 1);
    lr2 += __shfl_xor_sync(0xffffffffu, lr2, 2);
    if (tig == 0) {
        g_plsumA[chunk * N + r]  = lr;
        g_plsumA[chunk * N + r2] = lr2;
    }
    #pragma unroll
    for (int dn = 0; dn < 16; dn++) {
        size_t o1 = ((size_t)chunk * N + r) * D + 8 * dn + 2 * tig;
        size_t o2 = ((size_t)chunk * N + r2) * D + 8 * dn + 2 * tig;
        *(float2*)(g_partA + o1) = make_float2(acc[dn][0], acc[dn][1]);
        *(float2*)(g_partA + o2) = make_float2(acc[dn][2], acc[dn][3]);
    }
}

// ---------------- reduce chunks, normalize, squash, update p ----------------
template <bool FIRST>
__global__ void reduce_squash_kernel() {
    const int row  = (blockIdx.x * 256 + threadIdx.x) >> 5;
    const int lane = threadIdx.x & 31;
    float4 s4 = make_float4(0.f, 0.f, 0.f, 0.f);
    float ls = 0.f;
    #pragma unroll
    for (int c = 0; c < CHUNKS; c++) {
        const float4 v = *(const float4*)(g_partA + ((size_t)c * N + row) * D + lane * 4);
        s4.x += v.x; s4.y += v.y; s4.z += v.z; s4.w += v.w;
        ls += g_plsumA[c * N + row];
    }
    float inv = 1.f / ls;
    s4.x *= inv; s4.y *= inv; s4.z *= inv; s4.w *= inv;
    float nn = s4.x * s4.x + s4.y * s4.y + s4.z * s4.z + s4.w * s4.w;
    #pragma unroll
    for (int o = 16; o > 0; o >>= 1) nn += __shfl_xor_sync(0xffffffffu, nn, o);
    float nrm = sqrtf(nn);
    float f = nrm / ((1.f + nrm) * (nrm + 1e-8f));
    float4 p;
    if (FIRST) {
        p = make_float4(f * s4.x, f * s4.y, f * s4.z, f * s4.w);
    } else {
        const float4 po = *(const float4*)(g_pf + (size_t)row * D + lane * 4);
        p = make_float4(po.x + f * s4.x, po.y + f * s4.y, po.z + f * s4.z, po.w + f * s4.w);
    }
    *(float4*)(g_pf + (size_t)row * D + lane * 4) = p;
    *(uint32_t*)(g_p_hi + (size_t)row * D + lane * 4)     = pack2(p.x, p.y);
    *(uint32_t*)(g_p_hi + (size_t)row * D + lane * 4 + 2) = pack2(p.z, p.w);
}

// ---------------- out = squash(0.6*s_route + 0.4*s_attn) ----------------
__global__ void final_kernel(float* __restrict__ out) {
    const int row  = (blockIdx.x * 256 + threadIdx.x) >> 5;
    const int lane = threadIdx.x & 31;
    // routing branch
    float4 sa = make_float4(0.f, 0.f, 0.f, 0.f);
    float la = 0.f;
    #pragma unroll
    for (int c = 0; c < CHUNKS; c++) {
        const float4 va = *(const float4*)(g_partA + ((size_t)c * N + row) * D + lane * 4);
        sa.x += va.x; sa.y += va.y; sa.z += va.z; sa.w += va.w;
        la += g_plsumA[c * N + row];
    }
    // attention branch:
    //   positive set (hs+hd >= 0): SUFFIX [lo, N), weight e^{hs} e^{hd_j}
    //   negative set (hs+hd < 0):  PREFIX [0, lo), weight e^{0.2 hs} e^{0.2 hd_j}
    float hs = g_hs[row];
    float thr = -hs;
    int lo = 0, hi = N;
    while (lo < hi) {
        int m = (lo + hi) >> 1;
        if (g_hd_sorted[m] < thr) lo = m + 1; else hi = m;
    }
    const float* Pk = g_P + (size_t)lo * PCOLS;
    const float* Pt = g_P + (size_t)N * PCOLS;
    float e_hi = __expf(hs), e_lo = __expf(0.2f * hs);
    float4 p1  = *(const float4*)(Pk + lane * 4);
    float4 t1  = *(const float4*)(Pt + lane * 4);
    float4 p02 = *(const float4*)(Pk + 128 + lane * 4);
    float lattn = e_hi * (Pt[256] - Pk[256]) + e_lo * Pk[257];
    float4 num = make_float4(
        e_hi * (t1.x - p1.x) + e_lo * p02.x,
        e_hi * (t1.y - p1.y) + e_lo * p02.y,
        e_hi * (t1.z - p1.z) + e_lo * p02.z,
        e_hi * (t1.w - p1.w) + e_lo * p02.w);
    float ia = 0.6f / la, ib = 0.4f / lattn;
    float4 cm = make_float4(sa.x * ia + num.x * ib, sa.y * ia + num.y * ib,
                            sa.z * ia + num.z * ib, sa.w * ia + num.w * ib);
    float nn = cm.x * cm.x + cm.y * cm.y + cm.z * cm.z + cm.w * cm.w;
    #pragma unroll
    for (int o = 16; o > 0; o >>= 1) nn += __shfl_xor_sync(0xffffffffu, nn, o);
    float nrm = sqrtf(nn);
    float f = nrm / ((1.f + nrm) * (nrm + 1e-8f));
    *(float4*)(out + (size_t)row * D + lane * 4) =
        make_float4(cm.x * f, cm.y * f, cm.z * f, cm.w * f);
}

// ---------------- launch ----------------
extern "C" void kernel_launch(void* const* d_in, const int* in_sizes, int n_in,
                              void* d_out, int out_size) {
    (void)in_sizes; (void)n_in; (void)out_size;
    const float* h      = (const float*)d_in[0];
    const float* adj    = (const float*)d_in[1];
    const float* W      = (const float*)d_in[2];
    const float* attn_a = (const float*)d_in[3];
    float* out = (float*)d_out;

    static const size_t SMEM_NOP = 2 * TILE_BYTES + 256;   // 35072
    static const size_t SMEM_P   = 3 * TILE_BYTES + 256;   // 52480
    cudaFuncSetAttribute(flash_mma<true>,
                         cudaFuncAttributeMaxDynamicSharedMemorySize, (int)SMEM_P);

    rowsum_kernel<<<N, 256>>>((const float4*)adj);
    uhat_kernel<<<N / 4, 128>>>(h, W);
    hsd_kernel<<<N / 8, 256>>>((const float4*)h, (const float4*)attn_a);

    // attention branch precompute (sorted-prefix factorization)
    rank_kernel<<<N / 8, 256>>>();
    scan_p1_kernel<<<32, 288>>>();
    scan_p2_kernel<<<1, 288>>>();
    scan_p3_kernel<<<32, 288>>>();

    dim3 fg(N / 64, CHUNKS);
    flash_mma<false><<<fg, 128, SMEM_NOP>>>(adj);
    reduce_squash_kernel<true><<<N / 8, 256>>>();
    flash_mma<true><<<fg, 128, SMEM_P>>>(adj);
    reduce_squash_kernel<false><<<N / 8, 256>>>();
    flash_mma<true><<<fg, 128, SMEM_P>>>(adj);

    final_kernel<<<N / 8, 256>>>(out);
}